// round 1
// baseline (speedup 1.0000x reference)
#include <cuda_runtime.h>

// Problem constants (fixed for this problem instance)
#define NN   50000
#define EE   1600000
#define BB   128
#define MM   64
#define HH   32
#define FINF 20
#define KF   44            // folded K dimension: [x, x*f, de, rows*f, cols*f]
#define NCOL 2048          // M*H output columns
#define FEAT_STRIDE 100480 // padded 2*N (covers 2*98*512 = 100352), multiple of 128

// ---------------- device scratch (no allocations allowed) ----------------
__device__ float g_rows[NN * 4];
__device__ float g_cols[NN * 4];
__device__ int   g_diag[NN];
__device__ float g_nn[BB];
__device__ float g_sdp[BB * FINF];
__device__ float g_sa[BB * FINF];
__device__ float g_feat[KF * FEAT_STRIDE];   // duplicated features, k-major
__device__ float g_Wc[KF * NCOL];            // folded weights, k-major
__device__ float g_c[BB * NCOL];             // per-graph constant (basis 1,4 + bias)
__device__ float g_inv[BB * NCOL];           // per-graph accumulated relu sums

// ---------------- helpers ----------------
__device__ __forceinline__ void fma2(unsigned long long& d, unsigned long long a,
                                     unsigned long long b) {
    asm("fma.rn.f32x2 %0, %1, %2, %0;" : "+l"(d) : "l"(a), "l"(b));
}

// ---------------- K0: zero scratch (graph-replay safe) ----------------
__global__ void k_zero() {
    int i = blockIdx.x * blockDim.x + threadIdx.x;
    int stride = gridDim.x * blockDim.x;
    for (int j = i; j < NN * 4; j += stride) { g_rows[j] = 0.f; g_cols[j] = 0.f; }
    for (int j = i; j < NN; j += stride) g_diag[j] = -1;
    for (int j = i; j < BB; j += stride) g_nn[j] = 0.f;
    for (int j = i; j < BB * FINF; j += stride) { g_sdp[j] = 0.f; g_sa[j] = 0.f; }
    for (int j = i; j < BB * NCOL; j += stride) g_inv[j] = 0.f;
}

// ---------------- K1: node counts per graph ----------------
__global__ void k_count(const int* __restrict__ batch) {
    int n = blockIdx.x * blockDim.x + threadIdx.x;
    if (n < NN) atomicAdd(&g_nn[batch[n]], 1.0f);
}

// ---------------- K2: edge pass (rows/cols segment sums + diag scatter) ----------------
__global__ void k_edge(const int* __restrict__ ei, const float4* __restrict__ attr) {
    int e = blockIdx.x * blockDim.x + threadIdx.x;
    if (e >= EE) return;
    int s = ei[e];
    int d = ei[EE + e];
    float4 a = attr[e];
    atomicAdd(&g_rows[s * 4 + 0], a.x);
    atomicAdd(&g_rows[s * 4 + 1], a.y);
    atomicAdd(&g_rows[s * 4 + 2], a.z);
    atomicAdd(&g_rows[s * 4 + 3], a.w);
    atomicAdd(&g_cols[d * 4 + 0], a.x);
    atomicAdd(&g_cols[d * 4 + 1], a.y);
    atomicAdd(&g_cols[d * 4 + 2], a.z);
    atomicAdd(&g_cols[d * 4 + 3], a.w);
    if (s == d) atomicMax(&g_diag[s], e);  // last-write-wins == max edge index
}

// ---------------- K3: build folded per-node features + per-graph sums ----------------
__global__ void k_node(const float4* __restrict__ x4, const float4* __restrict__ attr,
                       const int* __restrict__ batch) {
    int n = blockIdx.x * blockDim.x + threadIdx.x;
    if (n >= NN) return;
    int b = batch[n];
    float f = 1.0f / g_nn[b];

    float xv[16];
    {
        float4 t0 = x4[n * 4 + 0], t1 = x4[n * 4 + 1], t2 = x4[n * 4 + 2], t3 = x4[n * 4 + 3];
        xv[0] = t0.x; xv[1] = t0.y; xv[2] = t0.z; xv[3] = t0.w;
        xv[4] = t1.x; xv[5] = t1.y; xv[6] = t1.z; xv[7] = t1.w;
        xv[8] = t2.x; xv[9] = t2.y; xv[10] = t2.z; xv[11] = t2.w;
        xv[12] = t3.x; xv[13] = t3.y; xv[14] = t3.z; xv[15] = t3.w;
    }
    int e = g_diag[n];
    float4 de = (e >= 0) ? attr[e] : make_float4(0.f, 0.f, 0.f, 0.f);
    float4 rr = *(const float4*)&g_rows[n * 4];
    float4 cc = *(const float4*)&g_cols[n * 4];

    float feat[KF];
#pragma unroll
    for (int j = 0; j < 16; j++) feat[j] = xv[j];
#pragma unroll
    for (int j = 0; j < 16; j++) feat[16 + j] = xv[j] * f;
    feat[32] = de.x; feat[33] = de.y; feat[34] = de.z; feat[35] = de.w;
    feat[36] = rr.x * f; feat[37] = rr.y * f; feat[38] = rr.z * f; feat[39] = rr.w * f;
    feat[40] = cc.x * f; feat[41] = cc.y * f; feat[42] = cc.z * f; feat[43] = cc.w * f;

#pragma unroll
    for (int k = 0; k < KF; k++) {
        float v = feat[k];
        *(float2*)&g_feat[k * FEAT_STRIDE + 2 * n] = make_float2(v, v);
    }

    // sum_diag_part (unscaled diag_part = [x, de])
#pragma unroll
    for (int j = 0; j < 16; j++) atomicAdd(&g_sdp[b * FINF + j], feat[j]);
    atomicAdd(&g_sdp[b * FINF + 16], de.x);
    atomicAdd(&g_sdp[b * FINF + 17], de.y);
    atomicAdd(&g_sdp[b * FINF + 18], de.z);
    atomicAdd(&g_sdp[b * FINF + 19], de.w);
    // sum of sum_of_cols = [x, cols] * f
#pragma unroll
    for (int j = 0; j < 16; j++) atomicAdd(&g_sa[b * FINF + j], feat[16 + j]);
    atomicAdd(&g_sa[b * FINF + 16], feat[40]);
    atomicAdd(&g_sa[b * FINF + 17], feat[41]);
    atomicAdd(&g_sa[b * FINF + 18], feat[42]);
    atomicAdd(&g_sa[b * FINF + 19], feat[43]);
}

// ---------------- K4: per-graph constant c[b][col] (basis 1 & 4 + bias_eq) ----------------
__global__ void k_c(const float* __restrict__ ke, const float* __restrict__ be) {
    int i = blockIdx.x * blockDim.x + threadIdx.x;
    if (i >= BB * NCOL) return;
    int b = i / NCOL, col = i - b * NCOL;
    int m = col >> 5, h = col & 31;
    float fb = 1.0f / g_nn[b];
    float fb2 = fb * fb;
    const float* k1 = ke + ((m * 5 + 1) * HH + h) * FINF;
    const float* k4 = ke + ((m * 5 + 4) * HH + h) * FINF;
    float acc = be[col];
#pragma unroll
    for (int f = 0; f < FINF; f++)
        acc += k1[f] * (g_sdp[b * FINF + f] * fb) + k4[f] * (g_sa[b * FINF + f] * fb2);
    g_c[i] = acc;
}

// ---------------- K5: folded weights Wc[k][col] ----------------
__global__ void k_w(const float* __restrict__ ke) {
    int col = blockIdx.x * blockDim.x + threadIdx.x;
    if (col >= NCOL) return;
    int m = col >> 5, h = col & 31;
    const float* k0 = ke + ((m * 5 + 0) * HH + h) * FINF;
    const float* k2 = ke + ((m * 5 + 2) * HH + h) * FINF;
    const float* k3 = ke + ((m * 5 + 3) * HH + h) * FINF;
#pragma unroll
    for (int f = 0; f < 16; f++) g_Wc[f * NCOL + col] = k0[f];
#pragma unroll
    for (int f = 0; f < 16; f++) g_Wc[(16 + f) * NCOL + col] = k2[f] + k3[f];
#pragma unroll
    for (int j = 0; j < 4; j++) g_Wc[(32 + j) * NCOL + col] = k0[16 + j];
#pragma unroll
    for (int j = 0; j < 4; j++) g_Wc[(36 + j) * NCOL + col] = k2[16 + j];
#pragma unroll
    for (int j = 0; j < 4; j++) g_Wc[(40 + j) * NCOL + col] = k3[16 + j];
}

// ---------------- K6: main fused GEMM + relu + per-graph reduce ----------------
// Block: 512 nodes (8 subtiles of 64) x 128 cols. Thread: 4 nodes x 8 cols, f32x2 packed.
__device__ __forceinline__ void flush_gacc(int cur_b, float* gacc, float* sg, int bfirst,
                                           int cg, int colbase) {
    if (cur_b < 0) return;
    int gi = cur_b - bfirst;
    if (gi >= 0 && gi < 4) {
#pragma unroll
        for (int j = 0; j < 8; j++) {
            atomicAdd(&sg[gi * 128 + cg * 8 + j], gacc[j]);
            gacc[j] = 0.f;
        }
    } else {
#pragma unroll
        for (int j = 0; j < 8; j++) {
            atomicAdd(&g_inv[cur_b * NCOL + colbase + cg * 8 + j], gacc[j]);
            gacc[j] = 0.f;
        }
    }
}

__global__ void __launch_bounds__(256) k_main(const int* __restrict__ batch) {
    __shared__ float wsm[KF * 128];  // split-half layout
    __shared__ float fsm[KF * 128];  // duplicated feats for 64 nodes
    __shared__ float sg[4 * 128];

    int tid = threadIdx.x;
    int cg = tid & 15;   // col group (8 cols)
    int ng = tid >> 4;   // node group (4 nodes)
    int colbase = blockIdx.y * 128;
    int nbase = blockIdx.x * 512;

    // load W tile: global group q (4 cols) -> smem [k*128 + (q&1)*64 + (q>>1)*4]
    for (int i = tid; i < KF * 32; i += 256) {
        int k = i >> 5, q = i & 31;
        float4 v = *(const float4*)&g_Wc[k * NCOL + colbase + q * 4];
        *(float4*)&wsm[k * 128 + (q & 1) * 64 + (q >> 1) * 4] = v;
    }
    for (int i = tid; i < 4 * 128; i += 256) sg[i] = 0.f;
    __syncthreads();

    int bfirst = batch[nbase < NN ? nbase : (NN - 1)];
    float gacc[8];
#pragma unroll
    for (int j = 0; j < 8; j++) gacc[j] = 0.f;
    int cur_b = -1;
    float cv[8];
#pragma unroll
    for (int j = 0; j < 8; j++) cv[j] = 0.f;

    const ulonglong2* W = (const ulonglong2*)wsm;
    const ulonglong2* F = (const ulonglong2*)fsm;

    for (int s = 0; s < 8; s++) {
        int gbase = 2 * nbase + s * 128;
        for (int i = tid; i < KF * 32; i += 256) {
            int k = i >> 5, q = i & 31;
            float4 v = *(const float4*)&g_feat[k * FEAT_STRIDE + gbase + q * 4];
            *(float4*)&fsm[k * 128 + q * 4] = v;
        }
        __syncthreads();

        unsigned long long acc[4][4];
#pragma unroll
        for (int i = 0; i < 4; i++)
#pragma unroll
            for (int p = 0; p < 4; p++) acc[i][p] = 0ull;

#pragma unroll
        for (int k = 0; k < KF; k++) {
            ulonglong2 wA = W[k * 32 + cg];       // cols 0-3 (pairs)
            ulonglong2 wB = W[k * 32 + 16 + cg];  // cols 4-7 (pairs)
            ulonglong2 fA = F[k * 32 + ng * 2];     // (n0,n0),(n1,n1)
            ulonglong2 fB = F[k * 32 + ng * 2 + 1]; // (n2,n2),(n3,n3)
            fma2(acc[0][0], fA.x, wA.x); fma2(acc[0][1], fA.x, wA.y);
            fma2(acc[0][2], fA.x, wB.x); fma2(acc[0][3], fA.x, wB.y);
            fma2(acc[1][0], fA.y, wA.x); fma2(acc[1][1], fA.y, wA.y);
            fma2(acc[1][2], fA.y, wB.x); fma2(acc[1][3], fA.y, wB.y);
            fma2(acc[2][0], fB.x, wA.x); fma2(acc[2][1], fB.x, wA.y);
            fma2(acc[2][2], fB.x, wB.x); fma2(acc[2][3], fB.x, wB.y);
            fma2(acc[3][0], fB.y, wA.x); fma2(acc[3][1], fB.y, wA.y);
            fma2(acc[3][2], fB.y, wB.x); fma2(acc[3][3], fB.y, wB.y);
        }
        __syncthreads();  // all reads of fsm done before next subtile load

        // epilogue: relu(z + c[b]) accumulate per graph
#pragma unroll
        for (int i = 0; i < 4; i++) {
            int n = nbase + s * 64 + ng * 4 + i;
            if (n < NN) {
                int b = __ldg(&batch[n]);
                if (b != cur_b) {
                    flush_gacc(cur_b, gacc, sg, bfirst, cg, colbase);
                    cur_b = b;
                    float4 c0 = *(const float4*)&g_c[b * NCOL + colbase + cg * 8];
                    float4 c1 = *(const float4*)&g_c[b * NCOL + colbase + cg * 8 + 4];
                    cv[0] = c0.x; cv[1] = c0.y; cv[2] = c0.z; cv[3] = c0.w;
                    cv[4] = c1.x; cv[5] = c1.y; cv[6] = c1.z; cv[7] = c1.w;
                }
#pragma unroll
                for (int p = 0; p < 4; p++) {
                    unsigned long long v = acc[i][p];
                    float lo = __uint_as_float((unsigned)(v & 0xffffffffull));
                    float hi = __uint_as_float((unsigned)(v >> 32));
                    gacc[2 * p]     += fmaxf(lo + cv[2 * p], 0.f);
                    gacc[2 * p + 1] += fmaxf(hi + cv[2 * p + 1], 0.f);
                }
            }
        }
    }
    flush_gacc(cur_b, gacc, sg, bfirst, cg, colbase);
    __syncthreads();

    for (int i = tid; i < 4 * 128; i += 256) {
        int gi = i >> 7, c = i & 127;
        int b = bfirst + gi;
        float v = sg[i];
        if (b < BB && v != 0.f) atomicAdd(&g_inv[b * NCOL + colbase + c], v);
    }
}

// ---------------- K7: final contraction (bias_inv cancels) ----------------
__global__ void k_out(const float* __restrict__ kinv, const float* __restrict__ be,
                      float* __restrict__ out) {
    int i = blockIdx.x * blockDim.x + threadIdx.x;
    if (i >= BB * MM) return;
    int b = i / MM, m = i - b * MM;
    float fb = 1.0f / g_nn[b];
    float s = 0.f;
#pragma unroll
    for (int h = 0; h < HH; h++) {
        float ib = g_inv[b * NCOL + m * HH + h] * fb;
        float zg = fmaxf(be[m * HH + h], 0.f);
        s += (ib - zg) * kinv[m * HH + h];
    }
    out[i] = s;
}

// ---------------- launch ----------------
extern "C" void kernel_launch(void* const* d_in, const int* in_sizes, int n_in,
                              void* d_out, int out_size) {
    const float4* x4   = (const float4*)d_in[0];
    const float4* attr = (const float4*)d_in[1];
    const float*  ke   = (const float*)d_in[2];
    const float*  kinv = (const float*)d_in[3];
    const float*  be   = (const float*)d_in[4];
    // d_in[5] = bias_inv (cancels in psi - zerograph)
    const int*    ei    = (const int*)d_in[6];
    const int*    batch = (const int*)d_in[7];
    float* out = (float*)d_out;

    k_zero<<<512, 256>>>();
    k_count<<<(NN + 255) / 256, 256>>>(batch);
    k_edge<<<(EE + 255) / 256, 256>>>(ei, attr);
    k_node<<<(NN + 255) / 256, 256>>>(x4, attr, batch);
    k_c<<<(BB * NCOL + 255) / 256, 256>>>(ke, be);
    k_w<<<(NCOL + 255) / 256, 256>>>(ke);
    dim3 grid((NN + 511) / 512, NCOL / 128);
    k_main<<<grid, 256>>>(batch);
    k_out<<<(BB * MM + 255) / 256, 256>>>(kinv, be, out);
}

// round 3
// speedup vs baseline: 1.0776x; 1.0776x over previous
#include <cuda_runtime.h>

// Problem constants (fixed for this problem instance)
#define NN   50000
#define EE   1600000
#define BB   128
#define MM   64
#define HH   32
#define FINF 20
#define KF   44            // folded K dimension: [x, x*f, de, rows*f, cols*f]
#define NCOL 2048          // M*H output columns
#define FEAT_STRIDE 100480 // padded 2*N (covers 2*98*512 = 100352), multiple of 128

// ---------------- device scratch (no allocations allowed) ----------------
__device__ float4 g_rows[NN];
__device__ float4 g_cols[NN];
__device__ int   g_diag[NN];
__device__ int   g_end[BB];
__device__ float g_nn[BB];
__device__ float g_sdp[BB * FINF];
__device__ float g_sa[BB * FINF];
__device__ float g_feat[KF * FEAT_STRIDE];   // duplicated features, k-major
__device__ float g_Wc[KF * NCOL];            // folded weights, k-major
__device__ float g_c[BB * NCOL];             // per-graph constant (basis 1,4 + bias)
__device__ float g_inv[BB * NCOL];           // per-graph accumulated relu sums

// ---------------- helpers ----------------
__device__ __forceinline__ void fma2(unsigned long long& d, unsigned long long a,
                                     unsigned long long b) {
    asm("fma.rn.f32x2 %0, %1, %2, %0;" : "+l"(d) : "l"(a), "l"(b));
}

// ---------------- K0: zero scratch (graph-replay safe) ----------------
__global__ void k_zero() {
    int i = blockIdx.x * blockDim.x + threadIdx.x;
    int stride = gridDim.x * blockDim.x;
    float4 z4 = make_float4(0.f, 0.f, 0.f, 0.f);
    for (int j = i; j < NN; j += stride) { g_rows[j] = z4; g_cols[j] = z4; g_diag[j] = -1; }
    for (int j = i; j < BB * FINF; j += stride) { g_sdp[j] = 0.f; g_sa[j] = 0.f; }
    for (int j = i; j < BB * NCOL; j += stride) g_inv[j] = 0.f;
}

// ---------------- K1a: segment boundaries (sorted batch, zero contention) ----------------
__global__ void k_bound(const int* __restrict__ batch) {
    int n = blockIdx.x * blockDim.x + threadIdx.x;
    if (n >= NN) return;
    int b = batch[n];
    int nb = (n + 1 < NN) ? batch[n + 1] : BB;
    if (nb != b) g_end[b] = n + 1;
}

// ---------------- K1b: counts from boundaries ----------------
__global__ void k_counts() {
    int b = threadIdx.x;
    if (b < BB) {
        int s = (b == 0) ? 0 : g_end[b - 1];
        g_nn[b] = (float)(g_end[b] - s);
    }
}

// ---------------- K2: edge pass (rows/cols segment sums + diag scatter) ----------------
__global__ void k_edge(const int* __restrict__ ei, const float4* __restrict__ attr) {
    int e = blockIdx.x * blockDim.x + threadIdx.x;
    if (e >= EE) return;
    int s = __ldg(&ei[e]);
    int d = __ldg(&ei[EE + e]);
    float4 a = attr[e];
    atomicAdd(&g_rows[s], a);   // sm_90+ vector red: one 16B RED instead of 4 scalar
    atomicAdd(&g_cols[d], a);
    if (s == d) atomicMax(&g_diag[s], e);  // last-write-wins == max edge index
}

// ---------------- K3: build folded per-node features + per-graph sums ----------------
// Block-level reduction: 256 consecutive sorted nodes span <= 2 graphs (min size 390).
__global__ void __launch_bounds__(256) k_node(const float4* __restrict__ x4,
                                              const float4* __restrict__ attr,
                                              const int* __restrict__ batch) {
    __shared__ float s_red[2 * 2 * FINF];   // [gi][sdp(20) | sa(20)]
    __shared__ int s_b0;
    int tid = threadIdx.x;
    int n0 = blockIdx.x * 256;
    int n = n0 + tid;
    if (tid < 2 * 2 * FINF) s_red[tid] = 0.f;
    if (tid == 0) s_b0 = batch[n0 < NN ? n0 : (NN - 1)];
    __syncthreads();

    if (n < NN) {
        int b = batch[n];
        float f = 1.0f / g_nn[b];

        float xv[16];
        {
            float4 t0 = x4[n * 4 + 0], t1 = x4[n * 4 + 1], t2 = x4[n * 4 + 2], t3 = x4[n * 4 + 3];
            xv[0] = t0.x; xv[1] = t0.y; xv[2] = t0.z; xv[3] = t0.w;
            xv[4] = t1.x; xv[5] = t1.y; xv[6] = t1.z; xv[7] = t1.w;
            xv[8] = t2.x; xv[9] = t2.y; xv[10] = t2.z; xv[11] = t2.w;
            xv[12] = t3.x; xv[13] = t3.y; xv[14] = t3.z; xv[15] = t3.w;
        }
        int e = g_diag[n];
        float4 de = (e >= 0) ? attr[e] : make_float4(0.f, 0.f, 0.f, 0.f);
        float4 rr = g_rows[n];
        float4 cc = g_cols[n];

        float feat[KF];
#pragma unroll
        for (int j = 0; j < 16; j++) feat[j] = xv[j];
#pragma unroll
        for (int j = 0; j < 16; j++) feat[16 + j] = xv[j] * f;
        feat[32] = de.x; feat[33] = de.y; feat[34] = de.z; feat[35] = de.w;
        feat[36] = rr.x * f; feat[37] = rr.y * f; feat[38] = rr.z * f; feat[39] = rr.w * f;
        feat[40] = cc.x * f; feat[41] = cc.y * f; feat[42] = cc.z * f; feat[43] = cc.w * f;

#pragma unroll
        for (int k = 0; k < KF; k++) {
            float v = feat[k];
            *(float2*)&g_feat[k * FEAT_STRIDE + 2 * n] = make_float2(v, v);
        }

        // Reduce into shared (warp-uniform addresses -> REDUX aggregation)
        int gi = (b != s_b0) ? 1 : 0;
        float* sr = &s_red[gi * 2 * FINF];
        // sum_diag_part (unscaled diag_part = [x, de])
#pragma unroll
        for (int j = 0; j < 16; j++) atomicAdd(&sr[j], feat[j]);
        atomicAdd(&sr[16], de.x);
        atomicAdd(&sr[17], de.y);
        atomicAdd(&sr[18], de.z);
        atomicAdd(&sr[19], de.w);
        // sum of sum_of_cols = [x, cols] * f
#pragma unroll
        for (int j = 0; j < 16; j++) atomicAdd(&sr[FINF + j], feat[16 + j]);
        atomicAdd(&sr[FINF + 16], feat[40]);
        atomicAdd(&sr[FINF + 17], feat[41]);
        atomicAdd(&sr[FINF + 18], feat[42]);
        atomicAdd(&sr[FINF + 19], feat[43]);
    }
    __syncthreads();

    // flush: 80 global atomics per block (vs 10240 before)
    if (tid < 2 * 2 * FINF) {
        int gi = tid / (2 * FINF);
        int j = tid - gi * (2 * FINF);
        int b = s_b0 + gi;
        float v = s_red[tid];
        if (b < BB && v != 0.f) {
            if (j < FINF) atomicAdd(&g_sdp[b * FINF + j], v);
            else          atomicAdd(&g_sa[b * FINF + (j - FINF)], v);
        }
    }
}

// ---------------- K4: per-graph constant c[b][col] (basis 1 & 4 + bias_eq) ----------------
__global__ void k_c(const float* __restrict__ ke, const float* __restrict__ be) {
    int i = blockIdx.x * blockDim.x + threadIdx.x;
    if (i >= BB * NCOL) return;
    int b = i / NCOL, col = i - b * NCOL;
    int m = col >> 5, h = col & 31;
    float fb = 1.0f / g_nn[b];
    float fb2 = fb * fb;
    const float* k1 = ke + ((m * 5 + 1) * HH + h) * FINF;
    const float* k4 = ke + ((m * 5 + 4) * HH + h) * FINF;
    float acc = be[col];
#pragma unroll
    for (int f = 0; f < FINF; f++)
        acc += k1[f] * (g_sdp[b * FINF + f] * fb) + k4[f] * (g_sa[b * FINF + f] * fb2);
    g_c[i] = acc;
}

// ---------------- K5: folded weights Wc[k][col] ----------------
__global__ void k_w(const float* __restrict__ ke) {
    int col = blockIdx.x * blockDim.x + threadIdx.x;
    if (col >= NCOL) return;
    int m = col >> 5, h = col & 31;
    const float* k0 = ke + ((m * 5 + 0) * HH + h) * FINF;
    const float* k2 = ke + ((m * 5 + 2) * HH + h) * FINF;
    const float* k3 = ke + ((m * 5 + 3) * HH + h) * FINF;
#pragma unroll
    for (int f = 0; f < 16; f++) g_Wc[f * NCOL + col] = k0[f];
#pragma unroll
    for (int f = 0; f < 16; f++) g_Wc[(16 + f) * NCOL + col] = k2[f] + k3[f];
#pragma unroll
    for (int j = 0; j < 4; j++) g_Wc[(32 + j) * NCOL + col] = k0[16 + j];
#pragma unroll
    for (int j = 0; j < 4; j++) g_Wc[(36 + j) * NCOL + col] = k2[16 + j];
#pragma unroll
    for (int j = 0; j < 4; j++) g_Wc[(40 + j) * NCOL + col] = k3[16 + j];
}

// ---------------- K6: main fused GEMM + relu + per-graph reduce ----------------
// Block: 512 nodes (8 subtiles of 64) x 128 cols. Thread: 4 nodes x 8 cols, f32x2 packed.
__device__ __forceinline__ void flush_gacc(int cur_b, float* gacc, float* sg, int bfirst,
                                           int cg, int colbase) {
    if (cur_b < 0) return;
    int gi = cur_b - bfirst;
    if (gi >= 0 && gi < 4) {
#pragma unroll
        for (int j = 0; j < 8; j++) {
            atomicAdd(&sg[gi * 128 + cg * 8 + j], gacc[j]);
            gacc[j] = 0.f;
        }
    } else {
#pragma unroll
        for (int j = 0; j < 8; j++) {
            atomicAdd(&g_inv[cur_b * NCOL + colbase + cg * 8 + j], gacc[j]);
            gacc[j] = 0.f;
        }
    }
}

__global__ void __launch_bounds__(256) k_main(const int* __restrict__ batch) {
    __shared__ float wsm[KF * 128];  // split-half layout
    __shared__ float fsm[KF * 128];  // duplicated feats for 64 nodes
    __shared__ float sg[4 * 128];

    int tid = threadIdx.x;
    int cg = tid & 15;   // col group (8 cols)
    int ng = tid >> 4;   // node group (4 nodes)
    int colbase = blockIdx.y * 128;
    int nbase = blockIdx.x * 512;

    // load W tile: global group q (4 cols) -> smem [k*128 + (q&1)*64 + (q>>1)*4]
    for (int i = tid; i < KF * 32; i += 256) {
        int k = i >> 5, q = i & 31;
        float4 v = *(const float4*)&g_Wc[k * NCOL + colbase + q * 4];
        *(float4*)&wsm[k * 128 + (q & 1) * 64 + (q >> 1) * 4] = v;
    }
    for (int i = tid; i < 4 * 128; i += 256) sg[i] = 0.f;
    __syncthreads();

    int bfirst = batch[nbase < NN ? nbase : (NN - 1)];
    float gacc[8];
#pragma unroll
    for (int j = 0; j < 8; j++) gacc[j] = 0.f;
    int cur_b = -1;
    float cv[8];
#pragma unroll
    for (int j = 0; j < 8; j++) cv[j] = 0.f;

    const ulonglong2* W = (const ulonglong2*)wsm;
    const ulonglong2* F = (const ulonglong2*)fsm;

    for (int s = 0; s < 8; s++) {
        int gbase = 2 * nbase + s * 128;
        for (int i = tid; i < KF * 32; i += 256) {
            int k = i >> 5, q = i & 31;
            float4 v = *(const float4*)&g_feat[k * FEAT_STRIDE + gbase + q * 4];
            *(float4*)&fsm[k * 128 + q * 4] = v;
        }
        __syncthreads();

        unsigned long long acc[4][4];
#pragma unroll
        for (int i = 0; i < 4; i++)
#pragma unroll
            for (int p = 0; p < 4; p++) acc[i][p] = 0ull;

#pragma unroll
        for (int k = 0; k < KF; k++) {
            ulonglong2 wA = W[k * 32 + cg];       // cols 0-3 (pairs)
            ulonglong2 wB = W[k * 32 + 16 + cg];  // cols 4-7 (pairs)
            ulonglong2 fA = F[k * 32 + ng * 2];     // (n0,n0),(n1,n1)
            ulonglong2 fB = F[k * 32 + ng * 2 + 1]; // (n2,n2),(n3,n3)
            fma2(acc[0][0], fA.x, wA.x); fma2(acc[0][1], fA.x, wA.y);
            fma2(acc[0][2], fA.x, wB.x); fma2(acc[0][3], fA.x, wB.y);
            fma2(acc[1][0], fA.y, wA.x); fma2(acc[1][1], fA.y, wA.y);
            fma2(acc[1][2], fA.y, wB.x); fma2(acc[1][3], fA.y, wB.y);
            fma2(acc[2][0], fB.x, wA.x); fma2(acc[2][1], fB.x, wA.y);
            fma2(acc[2][2], fB.x, wB.x); fma2(acc[2][3], fB.x, wB.y);
            fma2(acc[3][0], fB.y, wA.x); fma2(acc[3][1], fB.y, wA.y);
            fma2(acc[3][2], fB.y, wB.x); fma2(acc[3][3], fB.y, wB.y);
        }
        __syncthreads();  // all reads of fsm done before next subtile load

        // epilogue: relu(z + c[b]) accumulate per graph
#pragma unroll
        for (int i = 0; i < 4; i++) {
            int n = nbase + s * 64 + ng * 4 + i;
            if (n < NN) {
                int b = __ldg(&batch[n]);
                if (b != cur_b) {
                    flush_gacc(cur_b, gacc, sg, bfirst, cg, colbase);
                    cur_b = b;
                    float4 c0 = *(const float4*)&g_c[b * NCOL + colbase + cg * 8];
                    float4 c1 = *(const float4*)&g_c[b * NCOL + colbase + cg * 8 + 4];
                    cv[0] = c0.x; cv[1] = c0.y; cv[2] = c0.z; cv[3] = c0.w;
                    cv[4] = c1.x; cv[5] = c1.y; cv[6] = c1.z; cv[7] = c1.w;
                }
#pragma unroll
                for (int p = 0; p < 4; p++) {
                    unsigned long long v = acc[i][p];
                    float lo = __uint_as_float((unsigned)(v & 0xffffffffull));
                    float hi = __uint_as_float((unsigned)(v >> 32));
                    gacc[2 * p]     += fmaxf(lo + cv[2 * p], 0.f);
                    gacc[2 * p + 1] += fmaxf(hi + cv[2 * p + 1], 0.f);
                }
            }
        }
    }
    flush_gacc(cur_b, gacc, sg, bfirst, cg, colbase);
    __syncthreads();

    for (int i = tid; i < 4 * 128; i += 256) {
        int gi = i >> 7, c = i & 127;
        int b = bfirst + gi;
        float v = sg[i];
        if (b < BB && v != 0.f) atomicAdd(&g_inv[b * NCOL + colbase + c], v);
    }
}

// ---------------- K7: final contraction (bias_inv cancels) ----------------
__global__ void k_out(const float* __restrict__ kinv, const float* __restrict__ be,
                      float* __restrict__ out) {
    int i = blockIdx.x * blockDim.x + threadIdx.x;
    if (i >= BB * MM) return;
    int b = i / MM, m = i - b * MM;
    float fb = 1.0f / g_nn[b];
    float s = 0.f;
#pragma unroll
    for (int h = 0; h < HH; h++) {
        float ib = g_inv[b * NCOL + m * HH + h] * fb;
        float zg = fmaxf(be[m * HH + h], 0.f);
        s += (ib - zg) * kinv[m * HH + h];
    }
    out[i] = s;
}

// ---------------- launch ----------------
extern "C" void kernel_launch(void* const* d_in, const int* in_sizes, int n_in,
                              void* d_out, int out_size) {
    const float4* x4   = (const float4*)d_in[0];
    const float4* attr = (const float4*)d_in[1];
    const float*  ke   = (const float*)d_in[2];
    const float*  kinv = (const float*)d_in[3];
    const float*  be   = (const float*)d_in[4];
    // d_in[5] = bias_inv (cancels in psi - zerograph)
    const int*    ei    = (const int*)d_in[6];
    const int*    batch = (const int*)d_in[7];
    float* out = (float*)d_out;

    k_zero<<<512, 256>>>();
    k_bound<<<(NN + 255) / 256, 256>>>(batch);
    k_counts<<<1, 128>>>();
    k_edge<<<(EE + 255) / 256, 256>>>(ei, attr);
    k_node<<<(NN + 255) / 256, 256>>>(x4, attr, batch);
    k_c<<<(BB * NCOL + 255) / 256, 256>>>(ke, be);
    k_w<<<(NCOL + 255) / 256, 256>>>(ke);
    dim3 grid((NN + 511) / 512, NCOL / 128);
    k_main<<<grid, 256>>>(batch);
    k_out<<<(BB * MM + 255) / 256, 256>>>(kinv, be, out);
}